// round 1
// baseline (speedup 1.0000x reference)
#include <cuda_runtime.h>
#include <math.h>

#define B_SZ   2
#define LSEQ   1024
#define DMODEL 1024
#define DIN    2048
#define NST    16
#define DTR    64
#define MROWS  (B_SZ*LSEQ)   /* 2048 */
#define XP_N   96
#define SPLITS 8

// ---------------- scratch (device globals; no allocation allowed) ------------
__device__ float g_XZ[MROWS*8192];              // [m][dir*4096 + (xi:0..2047 | z:2048..4095)]
__device__ float g_U [MROWS*4096];              // [m][dir*2048 + d]   silu(conv)
__device__ float g_XDBLP[2*SPLITS*MROWS*XP_N];  // split-K partials
__device__ float g_XDBL [2*MROWS*XP_N];         // [dir][m][dt(64)|B(16)|C(16)]
__device__ float g_DELTA[2*(size_t)MROWS*DIN];  // [dir][m][d]
__device__ float g_YG[MROWS*4096];              // gated y: [m][dir*2048 + d]

// ---------------- generic fp32 SGEMM (C = A[M,K] * B[N,K]^T) -----------------
// EPI: 0=store, 1=softplus(acc+bias[n]), 2=store alpha*acc, 3=C += alpha*acc
template<int EPI>
__global__ __launch_bounds__(256, 2) void sgemm_nt(
    const float* __restrict__ A, int lda,
    const float* __restrict__ B, int ldb,
    float* __restrict__ C, int ldc,
    int M, int N, int K,
    const float* __restrict__ bias, float alpha, int ksplit)
{
    __shared__ float As[8][132];
    __shared__ float Bs[8][132];
    const int bm = blockIdx.y * 128;
    const int bn = blockIdx.x * 128;
    if (ksplit > 0) {                 // split-K: blockIdx.z selects K-chunk + output slice
        A += blockIdx.z * ksplit;
        B += blockIdx.z * ksplit;
        C += (size_t)blockIdx.z * (size_t)M * (size_t)ldc;
        K = ksplit;
    }
    const int tid = threadIdx.x;
    const int lr = tid >> 1;          // 0..127 tile row
    const int lc = (tid & 1) << 2;    // 0 or 4 (k sub-col)
    const int tx = tid & 15;
    const int ty = tid >> 4;

    const float* Aptr = A + (size_t)(bm + lr) * lda + lc;
    const float* Bptr = B + (size_t)(bn + lr) * ldb + lc;
    const bool bok = (bn + lr) < N;

    float acc[8][8];
#pragma unroll
    for (int i = 0; i < 8; i++)
#pragma unroll
        for (int j = 0; j < 8; j++) acc[i][j] = 0.f;

    float4 ra = *reinterpret_cast<const float4*>(Aptr);
    float4 rb = bok ? *reinterpret_cast<const float4*>(Bptr) : make_float4(0.f,0.f,0.f,0.f);

    const int nk = K >> 3;
    for (int kt = 0; kt < nk; kt++) {
        As[lc+0][lr] = ra.x; As[lc+1][lr] = ra.y; As[lc+2][lr] = ra.z; As[lc+3][lr] = ra.w;
        Bs[lc+0][lr] = rb.x; Bs[lc+1][lr] = rb.y; Bs[lc+2][lr] = rb.z; Bs[lc+3][lr] = rb.w;
        __syncthreads();
        if (kt + 1 < nk) {
            ra = *reinterpret_cast<const float4*>(Aptr + (kt+1)*8);
            rb = bok ? *reinterpret_cast<const float4*>(Bptr + (kt+1)*8)
                     : make_float4(0.f,0.f,0.f,0.f);
        }
#pragma unroll
        for (int k = 0; k < 8; k++) {
            float4 a0 = *reinterpret_cast<const float4*>(&As[k][ty*8]);
            float4 a1 = *reinterpret_cast<const float4*>(&As[k][ty*8+4]);
            float4 b0 = *reinterpret_cast<const float4*>(&Bs[k][tx*8]);
            float4 b1 = *reinterpret_cast<const float4*>(&Bs[k][tx*8+4]);
            float av[8] = {a0.x,a0.y,a0.z,a0.w,a1.x,a1.y,a1.z,a1.w};
            float bv[8] = {b0.x,b0.y,b0.z,b0.w,b1.x,b1.y,b1.z,b1.w};
#pragma unroll
            for (int i = 0; i < 8; i++)
#pragma unroll
                for (int j = 0; j < 8; j++)
                    acc[i][j] = fmaf(av[i], bv[j], acc[i][j]);
        }
        __syncthreads();
    }

#pragma unroll
    for (int i = 0; i < 8; i++) {
        const int m = bm + ty*8 + i;
        float* crow = C + (size_t)m * ldc;
#pragma unroll
        for (int j = 0; j < 8; j++) {
            const int nn = bn + tx*8 + j;
            if (nn < N) {
                float v = acc[i][j];
                if (EPI == 1) { v += bias[nn]; v = (v > 20.f) ? v : log1pf(__expf(v)); }
                else if (EPI == 2) { v *= alpha; }
                else if (EPI == 3) { v = crow[nn] + alpha * v; }
                crow[nn] = v;
            }
        }
    }
}

// ------------- depthwise conv (causal fwd / anti-causal bwd) + SiLU ----------
__global__ __launch_bounds__(256) void conv_silu_kernel(
    const float* __restrict__ convW_f, const float* __restrict__ convB_f,
    const float* __restrict__ convW_b, const float* __restrict__ convB_b)
{
    const int i = blockIdx.x * 256 + threadIdx.x;   // over MROWS*4096
    const int c = i & 4095;
    const int row = i >> 12;                        // b*LSEQ + l
    const int l = row & (LSEQ - 1);
    const int b = row >> 10;
    const int dir = c >> 11;
    const int d = c & (DIN - 1);
    const float* w = (dir ? convW_b : convW_f) + d*4;
    float acc = (dir ? convB_b : convB_f)[d];
    const float* xi = g_XZ + dir*4096 + d;
    if (dir == 0) {
#pragma unroll
        for (int k = 0; k < 4; k++) {
            int ls = l - 3 + k;
            if (ls >= 0) acc = fmaf(w[k], xi[(size_t)(b*LSEQ + ls)*8192], acc);
        }
    } else {
#pragma unroll
        for (int k = 0; k < 4; k++) {
            int ls = l + 3 - k;
            if (ls < LSEQ) acc = fmaf(w[k], xi[(size_t)(b*LSEQ + ls)*8192], acc);
        }
    }
    const float sig = 1.f / (1.f + __expf(-acc));
    g_U[(size_t)row*4096 + c] = acc * sig;
}

// ------------------------- split-K partial reduction -------------------------
__global__ __launch_bounds__(256) void reduce_xdbl_kernel()
{
    const int i = blockIdx.x * 256 + threadIdx.x;   // over 2*MROWS*XP_N
    const int dir = i / (MROWS*XP_N);
    const int r = i - dir*(MROWS*XP_N);
    const float* p = g_XDBLP + (size_t)dir*SPLITS*MROWS*XP_N + r;
    float s = 0.f;
#pragma unroll
    for (int k = 0; k < SPLITS; k++) s += p[(size_t)k*MROWS*XP_N];
    g_XDBL[(size_t)dir*MROWS*XP_N + r] = s;
}

// ------------------- selective scan + gating (both directions) ---------------
// block: (d-block of 16, batch, dir); thread t -> (dl = t/16 state-channel d, n = t%16)
__global__ __launch_bounds__(256) void scan_kernel(
    const float* __restrict__ Alog_f, const float* __restrict__ Alog_b,
    const float* __restrict__ Dp_f,  const float* __restrict__ Dp_b)
{
    const int dir = blockIdx.z;
    const int b   = blockIdx.y;
    const int d0  = blockIdx.x * 16;
    const int t  = threadIdx.x;
    const int dl = t >> 4;
    const int n  = t & 15;
    const int d  = d0 + dl;

    const float Acoef = -__expf((dir ? Alog_b : Alog_f)[d*NST + n]);
    const float DpV   = (dir ? Dp_b : Dp_f)[d];

    __shared__ float sD[32][16], sU[32][16], sZ[32][16], sB2[32][16], sC2[32][16];

    const float* DELTA = g_DELTA + (size_t)dir * MROWS * DIN;
    const float* XDBL  = g_XDBL  + (size_t)dir * MROWS * XP_N;

    const int idx0 = t, idx1 = t + 256;
    const int la0 = idx0 >> 4, qa0 = idx0 & 15;
    const int la1 = idx1 >> 4, qa1 = idx1 & 15;

    float rg[10];
    {   // prologue load: chunk 0
        const int lb = (dir == 0) ? 0 : (LSEQ - 32);
        const int row0 = b*LSEQ + lb + la0;
        const int row1 = b*LSEQ + lb + la1;
        rg[0] = DELTA[(size_t)row0*DIN + d0 + qa0];
        rg[1] = DELTA[(size_t)row1*DIN + d0 + qa1];
        rg[2] = g_U[(size_t)row0*4096 + dir*2048 + d0 + qa0];
        rg[3] = g_U[(size_t)row1*4096 + dir*2048 + d0 + qa1];
        rg[4] = g_XZ[(size_t)row0*8192 + dir*4096 + 2048 + d0 + qa0];
        rg[5] = g_XZ[(size_t)row1*8192 + dir*4096 + 2048 + d0 + qa1];
        rg[6] = XDBL[(size_t)row0*XP_N + DTR + qa0];
        rg[7] = XDBL[(size_t)row1*XP_N + DTR + qa1];
        rg[8] = XDBL[(size_t)row0*XP_N + DTR + NST + qa0];
        rg[9] = XDBL[(size_t)row1*XP_N + DTR + NST + qa1];
    }

    float h = 0.f;
    const int NCH = LSEQ / 32;
    for (int c = 0; c < NCH; c++) {
        __syncthreads();
        sD [la0][qa0] = rg[0]; sD [la1][qa1] = rg[1];
        sU [la0][qa0] = rg[2]; sU [la1][qa1] = rg[3];
        sZ [la0][qa0] = rg[4]; sZ [la1][qa1] = rg[5];
        sB2[la0][qa0] = rg[6]; sB2[la1][qa1] = rg[7];
        sC2[la0][qa0] = rg[8]; sC2[la1][qa1] = rg[9];
        __syncthreads();
        if (c + 1 < NCH) {   // prefetch next chunk into registers (latency hidden by compute)
            const int lb = (dir == 0) ? (c+1)*32 : (LSEQ - (c+2)*32);
            const int row0 = b*LSEQ + lb + la0;
            const int row1 = b*LSEQ + lb + la1;
            rg[0] = DELTA[(size_t)row0*DIN + d0 + qa0];
            rg[1] = DELTA[(size_t)row1*DIN + d0 + qa1];
            rg[2] = g_U[(size_t)row0*4096 + dir*2048 + d0 + qa0];
            rg[3] = g_U[(size_t)row1*4096 + dir*2048 + d0 + qa1];
            rg[4] = g_XZ[(size_t)row0*8192 + dir*4096 + 2048 + d0 + qa0];
            rg[5] = g_XZ[(size_t)row1*8192 + dir*4096 + 2048 + d0 + qa1];
            rg[6] = XDBL[(size_t)row0*XP_N + DTR + qa0];
            rg[7] = XDBL[(size_t)row1*XP_N + DTR + qa1];
            rg[8] = XDBL[(size_t)row0*XP_N + DTR + NST + qa0];
            rg[9] = XDBL[(size_t)row1*XP_N + DTR + NST + qa1];
        }
        const int lb = (dir == 0) ? c*32 : (LSEQ - (c+1)*32);
#pragma unroll 4
        for (int s = 0; s < 32; s++) {
            const int ll = (dir == 0) ? s : (31 - s);
            const float del = sD[ll][dl];
            const float uu  = sU[ll][dl];
            const float dA  = __expf(del * Acoef);
            h = fmaf(h, dA, del * uu * sB2[ll][n]);
            float py = h * sC2[ll][n];
            py += __shfl_xor_sync(0xffffffffu, py, 8);
            py += __shfl_xor_sync(0xffffffffu, py, 4);
            py += __shfl_xor_sync(0xffffffffu, py, 2);
            py += __shfl_xor_sync(0xffffffffu, py, 1);
            if (n == 0) {
                const float zz = sZ[ll][dl];
                const float y = fmaf(uu, DpV, py);
                const float sig = 1.f / (1.f + __expf(-zz));
                g_YG[(size_t)(b*LSEQ + lb + ll)*4096 + dir*2048 + d] = y * (zz * sig);
            }
        }
    }
}

// ------------------------------------ launch ---------------------------------
extern "C" void kernel_launch(void* const* d_in, const int* in_sizes, int n_in,
                              void* d_out, int out_size)
{
    const float* x      = (const float*)d_in[0];
    const float* inW_f  = (const float*)d_in[1];
    const float* convW_f= (const float*)d_in[2];
    const float* convB_f= (const float*)d_in[3];
    const float* xpW_f  = (const float*)d_in[4];
    const float* dtW_f  = (const float*)d_in[5];
    const float* dtB_f  = (const float*)d_in[6];
    const float* Alog_f = (const float*)d_in[7];
    const float* Dp_f   = (const float*)d_in[8];
    const float* outW_f = (const float*)d_in[9];
    const float* inW_b  = (const float*)d_in[10];
    const float* convW_b= (const float*)d_in[11];
    const float* convB_b= (const float*)d_in[12];
    const float* xpW_b  = (const float*)d_in[13];
    const float* dtW_b  = (const float*)d_in[14];
    const float* dtB_b  = (const float*)d_in[15];
    const float* Alog_b = (const float*)d_in[16];
    const float* Dp_b   = (const float*)d_in[17];
    const float* outW_b = (const float*)d_in[18];
    float* out = (float*)d_out;

    float *XZ, *U, *XDBLP, *XDBL, *DELTA, *YG;
    cudaGetSymbolAddress((void**)&XZ,    g_XZ);
    cudaGetSymbolAddress((void**)&U,     g_U);
    cudaGetSymbolAddress((void**)&XDBLP, g_XDBLP);
    cudaGetSymbolAddress((void**)&XDBL,  g_XDBL);
    cudaGetSymbolAddress((void**)&DELTA, g_DELTA);
    cudaGetSymbolAddress((void**)&YG,    g_YG);

    // 1) input projection (both directions; flip folded into conv/scan direction)
    sgemm_nt<0><<<dim3(32,16,1), 256>>>(x, DMODEL, inW_f, DMODEL, XZ,      8192, MROWS, 4096, DMODEL, nullptr, 1.f, 0);
    sgemm_nt<0><<<dim3(32,16,1), 256>>>(x, DMODEL, inW_b, DMODEL, XZ+4096, 8192, MROWS, 4096, DMODEL, nullptr, 1.f, 0);

    // 2) depthwise conv + SiLU
    conv_silu_kernel<<<(MROWS*4096)/256, 256>>>(convW_f, convB_f, convW_b, convB_b);

    // 3) x_dbl projection (N=96) with split-K=8 + deterministic reduce
    sgemm_nt<0><<<dim3(1,16,SPLITS), 256>>>(U,      4096, xpW_f, DIN, XDBLP,                    XP_N, MROWS, XP_N, DIN, nullptr, 1.f, DIN/SPLITS);
    sgemm_nt<0><<<dim3(1,16,SPLITS), 256>>>(U+2048, 4096, xpW_b, DIN, XDBLP+SPLITS*MROWS*XP_N,  XP_N, MROWS, XP_N, DIN, nullptr, 1.f, DIN/SPLITS);
    reduce_xdbl_kernel<<<(2*MROWS*XP_N)/256, 256>>>();

    // 4) delta = softplus(dt @ dtW^T + dtB)
    sgemm_nt<1><<<dim3(16,16,1), 256>>>(XDBL,              XP_N, dtW_f, DTR, DELTA,            DIN, MROWS, DIN, DTR, dtB_f, 1.f, 0);
    sgemm_nt<1><<<dim3(16,16,1), 256>>>(XDBL+MROWS*XP_N,   XP_N, dtW_b, DTR, DELTA+MROWS*DIN,  DIN, MROWS, DIN, DTR, dtB_b, 1.f, 0);

    // 5) selective scan + gating (fwd ascending, bwd descending; fuses (y+u*D)*silu(z))
    scan_kernel<<<dim3(128,2,2), 256>>>(Alog_f, Alog_b, Dp_f, Dp_b);

    // 6) output projection, out = 0.5*(yg_f @ outW_f^T + yg_b @ outW_b^T)
    sgemm_nt<2><<<dim3(8,16,1), 256>>>(YG,      4096, outW_f, DIN, out, DMODEL, MROWS, DMODEL, DIN, nullptr, 0.5f, 0);
    sgemm_nt<3><<<dim3(8,16,1), 256>>>(YG+2048, 4096, outW_b, DIN, out, DMODEL, MROWS, DMODEL, DIN, nullptr, 0.5f, 0);
}

// round 3
// speedup vs baseline: 1.9491x; 1.9491x over previous
#include <cuda_runtime.h>
#include <cuda_bf16.h>
#include <math.h>
#include <cstdint>

#define B_SZ   2
#define LSEQ   1024
#define DMODEL 1024
#define DIN    2048
#define NST    16
#define DTR    64
#define MROWS  (B_SZ*LSEQ)   /* 2048 */

// ---------------- scratch (device globals; no allocation allowed) ------------
__device__ float g_XZ[MROWS*8192];              // [m][dir*4096 + (xi:0..2047 | z:2048..4095)]
__device__ float g_U [MROWS*4096];              // [m][dir*2048 + d]   silu(conv)
__device__ float g_XDBLP[4*MROWS*256];          // split-K partials for x_dbl
__device__ float g_XDBL[MROWS*256];             // [m][dir*128 + (dt:0..63 | B:64..79 | C:80..95)]
__device__ float g_DELTA[(size_t)MROWS*4096];   // [m][dir*2048 + d]
__device__ float g_YG[MROWS*4096];              // gated y: [m][dir*2048 + d]

// ======================= HMMA GEMM (mma.sync bf16, fp32 via bf16x3) ==========
// C[M,N] = A[M,K] * B[N,K]^T   (A row-major, B row-major over [N,K])
// B element (n,k): if (nsplit && n>=nsplit) -> B1[n-nsplit][k]
//                  elif (ksel && k>=ksel)   -> B1[n][k-ksel]     else B0[n][k]
// B rows >= brows (per part) are zero. A += a_off1 when CTA n-tile >= nsplit.
// kz>0: split-K, blockIdx.z picks K chunk, C offset by z*M*ldc (partials).
// EPI: 0 = store, 1 = softplus(acc + bias[n]), 2 = store alpha*acc

#define BKC 32
#define ASTRIDE 80             /* bytes per smem row: 32 bf16 + 8 pad */
#define STG_A_HI 0
#define STG_A_LO 10240
#define STG_B_HI 20480
#define STG_B_LO 30720
#define STG_STRIDE 40960
#define HG_SMEM (2*STG_STRIDE)

__device__ __forceinline__ uint32_t smem_u32(const void* p) {
    uint32_t a;
    asm("{ .reg .u64 t; cvta.to.shared.u64 t, %1; cvt.u32.u64 %0, t; }" : "=r"(a) : "l"(p));
    return a;
}

#define LDM4(r0,r1,r2,r3,addr)                                                      \
    asm volatile("ldmatrix.sync.aligned.m8n8.x4.shared.b16 {%0,%1,%2,%3}, [%4];"    \
        : "=r"(r0),"=r"(r1),"=r"(r2),"=r"(r3) : "r"(addr))

#define MMA16816(c,a,b)                                                             \
    asm volatile("mma.sync.aligned.m16n8k16.row.col.f32.bf16.bf16.f32 "             \
        "{%0,%1,%2,%3}, {%4,%5,%6,%7}, {%8,%9}, {%0,%1,%2,%3};"                     \
        : "+f"((c)[0]),"+f"((c)[1]),"+f"((c)[2]),"+f"((c)[3])                       \
        : "r"((a)[0]),"r"((a)[1]),"r"((a)[2]),"r"((a)[3]),"r"((b)[0]),"r"((b)[1]))

__device__ __forceinline__ uint32_t pack2(float x, float y) {
    __nv_bfloat162 t = __floats2bfloat162_rn(x, y);
    return *reinterpret_cast<uint32_t*>(&t);
}
__device__ __forceinline__ void cvt8(float4 v0, float4 v1, uint4& hi, uint4& lo) {
    float f[8] = {v0.x, v0.y, v0.z, v0.w, v1.x, v1.y, v1.z, v1.w};
    float l[8];
#pragma unroll
    for (int i = 0; i < 8; i++) {
        __nv_bfloat16 h = __float2bfloat16(f[i]);
        l[i] = f[i] - __bfloat162float(h);
    }
    hi = make_uint4(pack2(f[0],f[1]), pack2(f[2],f[3]), pack2(f[4],f[5]), pack2(f[6],f[7]));
    lo = make_uint4(pack2(l[0],l[1]), pack2(l[2],l[3]), pack2(l[4],l[5]), pack2(l[6],l[7]));
}

template<int EPI>
__global__ __launch_bounds__(256, 1) void hgemm(
    const float* __restrict__ A, int lda, int a_off1,
    const float* __restrict__ B0, const float* __restrict__ B1, int ldb,
    int brows, int nsplit, int ksel,
    float* __restrict__ C, int ldc, int K,
    const float* __restrict__ bias0, const float* __restrict__ bias1,
    float alpha, int kz)
{
    extern __shared__ char sm[];
    const uint32_t smb = smem_u32(sm);
    const int tid = threadIdx.x;
    const int bm = blockIdx.y * 128, bn = blockIdx.x * 128;
    if (kz > 0) {
        A  += (size_t)blockIdx.z * kz;
        B0 += (size_t)blockIdx.z * kz;
        B1 += (size_t)blockIdx.z * kz;
        C  += (size_t)blockIdx.z * (size_t)(gridDim.y * 128) * (size_t)ldc;
        K = kz;
    }
    const float* Ae = A + ((nsplit && bn >= nsplit) ? a_off1 : 0);

    // ---- global staging roles: each thread loads half a 32-col row ----------
    const int grow = tid >> 1;
    const int gcol = (tid & 1) << 4;       // 0 or 16

    int nn = bn + grow;
    const float* Bsel = B0;
    if (nsplit && nn >= nsplit) { Bsel = B1; nn -= nsplit; }
    const bool bvalid = (nn < brows);
    const size_t arow_off = (size_t)(bm + grow) * lda + gcol;
    const size_t brow_off = (size_t)nn * ldb;

    // ---- warp geometry ------------------------------------------------------
    const int wid = tid >> 5, lane = tid & 31;
    const int wm = (wid >> 2) * 64;
    const int wn = (wid & 3) * 32;
    const int tq = lane >> 2, tr = lane & 3;

    // ldmatrix base offsets (within stage)
    const uint32_t aoff = (uint32_t)((wm + (lane & 15)) * ASTRIDE + ((lane >> 4) << 4));
    const int g = lane >> 3;
    const uint32_t boff = (uint32_t)((wn + ((g >> 1) << 3) + (lane & 7)) * ASTRIDE + ((g & 1) << 4));

    float acc[4][4][4];
#pragma unroll
    for (int i = 0; i < 4; i++)
#pragma unroll
        for (int j = 0; j < 4; j++)
#pragma unroll
            for (int q = 0; q < 4; q++) acc[i][j][q] = 0.f;

    const int nch = K / BKC;
    float4 ra[4], rb[4];

    // ---- load one chunk's worth of A/B into registers -----------------------
    auto loadg = [&](int kc) {
        const float* ap = Ae + arow_off + kc;
#pragma unroll
        for (int q = 0; q < 4; q++) ra[q] = *reinterpret_cast<const float4*>(ap + q*4);
        int kk = kc + gcol;
        const float* Bp = Bsel;
        if (ksel && kk >= ksel) { Bp = B1; kk -= ksel; }
        if (bvalid) {
            const float* bp2 = Bp + brow_off + kk;
#pragma unroll
            for (int q = 0; q < 4; q++) rb[q] = *reinterpret_cast<const float4*>(bp2 + q*4);
        } else {
#pragma unroll
            for (int q = 0; q < 4; q++) rb[q] = make_float4(0.f,0.f,0.f,0.f);
        }
    };
    // ---- convert + store staged regs into smem stage ------------------------
    auto storest = [&](int stg) {
        char* sp = sm + stg * STG_STRIDE;
        const uint32_t oa = grow * ASTRIDE + gcol * 2;
        uint4 h0,l0,h1,l1;
        cvt8(ra[0], ra[1], h0, l0); cvt8(ra[2], ra[3], h1, l1);
        *reinterpret_cast<uint4*>(sp + STG_A_HI + oa)      = h0;
        *reinterpret_cast<uint4*>(sp + STG_A_HI + oa + 16) = h1;
        *reinterpret_cast<uint4*>(sp + STG_A_LO + oa)      = l0;
        *reinterpret_cast<uint4*>(sp + STG_A_LO + oa + 16) = l1;
        cvt8(rb[0], rb[1], h0, l0); cvt8(rb[2], rb[3], h1, l1);
        *reinterpret_cast<uint4*>(sp + STG_B_HI + oa)      = h0;
        *reinterpret_cast<uint4*>(sp + STG_B_HI + oa + 16) = h1;
        *reinterpret_cast<uint4*>(sp + STG_B_LO + oa)      = l0;
        *reinterpret_cast<uint4*>(sp + STG_B_LO + oa + 16) = l1;
    };

    loadg(0);
    storest(0);
    __syncthreads();

    for (int s = 0; s < nch; s++) {
        if (s + 1 < nch) loadg((s + 1) * BKC);   // LDGs in flight under the MMAs
        const uint32_t sa = smb + (uint32_t)(s & 1) * STG_STRIDE;
#pragma unroll
        for (int ph = 0; ph < 2; ph++) {
            const uint32_t ka = sa + ph * 32;    // +16 bf16 per k-phase
            uint32_t ah[4][4], al[4][4], bh[4][2], bl[4][2];
#pragma unroll
            for (int i = 0; i < 4; i++)
                LDM4(ah[i][0], ah[i][1], ah[i][2], ah[i][3], ka + STG_A_HI + aoff + i*(16*ASTRIDE));
#pragma unroll
            for (int i = 0; i < 4; i++)
                LDM4(al[i][0], al[i][1], al[i][2], al[i][3], ka + STG_A_LO + aoff + i*(16*ASTRIDE));
            LDM4(bh[0][0], bh[0][1], bh[1][0], bh[1][1], ka + STG_B_HI + boff);
            LDM4(bh[2][0], bh[2][1], bh[3][0], bh[3][1], ka + STG_B_HI + boff + 16*ASTRIDE);
            LDM4(bl[0][0], bl[0][1], bl[1][0], bl[1][1], ka + STG_B_LO + boff);
            LDM4(bl[2][0], bl[2][1], bl[3][0], bl[3][1], ka + STG_B_LO + boff + 16*ASTRIDE);
#pragma unroll
            for (int i = 0; i < 4; i++)
#pragma unroll
                for (int j = 0; j < 4; j++) {
                    MMA16816(acc[i][j], ah[i], bh[j]);
                    MMA16816(acc[i][j], ah[i], bl[j]);
                    MMA16816(acc[i][j], al[i], bh[j]);
                }
        }
        if (s + 1 < nch) storest((s + 1) & 1);
        __syncthreads();
    }

    // ---- epilogue -----------------------------------------------------------
    const float* bias = nullptr;
    if (EPI == 1) bias = (nsplit && bn >= nsplit) ? (bias1 - nsplit) : bias0;
#pragma unroll
    for (int i = 0; i < 4; i++) {
        const int row0 = bm + wm + 16*i + tq;
#pragma unroll
        for (int j = 0; j < 4; j++) {
            const int col = bn + wn + 8*j + 2*tr;
            float v0 = acc[i][j][0], v1 = acc[i][j][1];
            float v2 = acc[i][j][2], v3 = acc[i][j][3];
            if (EPI == 1) {
                const float b0v = bias[col], b1v = bias[col+1];
                v0 += b0v; v1 += b1v; v2 += b0v; v3 += b1v;
                v0 = (v0 > 20.f) ? v0 : log1pf(__expf(v0));
                v1 = (v1 > 20.f) ? v1 : log1pf(__expf(v1));
                v2 = (v2 > 20.f) ? v2 : log1pf(__expf(v2));
                v3 = (v3 > 20.f) ? v3 : log1pf(__expf(v3));
            } else if (EPI == 2) {
                v0 *= alpha; v1 *= alpha; v2 *= alpha; v3 *= alpha;
            }
            *reinterpret_cast<float2*>(C + (size_t)row0 * ldc + col)       = make_float2(v0, v1);
            *reinterpret_cast<float2*>(C + (size_t)(row0 + 8) * ldc + col) = make_float2(v2, v3);
        }
    }
}

// ------------- depthwise conv (causal fwd / anti-causal bwd) + SiLU ----------
__global__ __launch_bounds__(256) void conv_silu_kernel(
    const float* __restrict__ convW_f, const float* __restrict__ convB_f,
    const float* __restrict__ convW_b, const float* __restrict__ convB_b)
{
    const int i = blockIdx.x * 256 + threadIdx.x;   // over MROWS*4096
    const int c = i & 4095;
    const int row = i >> 12;                        // b*LSEQ + l
    const int l = row & (LSEQ - 1);
    const int b = row >> 10;
    const int dir = c >> 11;
    const int d = c & (DIN - 1);
    const float* w = (dir ? convW_b : convW_f) + d*4;
    float acc = (dir ? convB_b : convB_f)[d];
    const float* xi = g_XZ + dir*4096 + d;
    if (dir == 0) {
#pragma unroll
        for (int k = 0; k < 4; k++) {
            int ls = l - 3 + k;
            if (ls >= 0) acc = fmaf(w[k], xi[(size_t)(b*LSEQ + ls)*8192], acc);
        }
    } else {
#pragma unroll
        for (int k = 0; k < 4; k++) {
            int ls = l + 3 - k;
            if (ls < LSEQ) acc = fmaf(w[k], xi[(size_t)(b*LSEQ + ls)*8192], acc);
        }
    }
    const float sig = 1.f / (1.f + __expf(-acc));
    g_U[(size_t)row*4096 + c] = acc * sig;
}

// ------------------------- split-K partial reduction -------------------------
__global__ __launch_bounds__(256) void reduce_xdbl_kernel()
{
    const int i = blockIdx.x * 256 + threadIdx.x;   // over MROWS*256
    float s = 0.f;
#pragma unroll
    for (int k = 0; k < 4; k++) s += g_XDBLP[(size_t)k*MROWS*256 + i];
    g_XDBL[i] = s;
}

// ------------------- selective scan + gating (both directions) ---------------
__global__ __launch_bounds__(256) void scan_kernel(
    const float* __restrict__ Alog_f, const float* __restrict__ Alog_b,
    const float* __restrict__ Dp_f,  const float* __restrict__ Dp_b)
{
    const int dir = blockIdx.z;
    const int b   = blockIdx.y;
    const int d0  = blockIdx.x * 16;
    const int t  = threadIdx.x;
    const int dl = t >> 4;
    const int n  = t & 15;
    const int d  = d0 + dl;

    const float Acoef = -__expf((dir ? Alog_b : Alog_f)[d*NST + n]);
    const float DpV   = (dir ? Dp_b : Dp_f)[d];

    __shared__ float sD[32][16], sU[32][16], sZ[32][16], sB2[32][16], sC2[32][16];

    const int idx0 = t, idx1 = t + 256;
    const int la0 = idx0 >> 4, qa0 = idx0 & 15;
    const int la1 = idx1 >> 4, qa1 = idx1 & 15;

    float rg[10];
    {   // prologue load: chunk 0
        const int lb = (dir == 0) ? 0 : (LSEQ - 32);
        const int row0 = b*LSEQ + lb + la0;
        const int row1 = b*LSEQ + lb + la1;
        rg[0] = g_DELTA[(size_t)row0*4096 + dir*2048 + d0 + qa0];
        rg[1] = g_DELTA[(size_t)row1*4096 + dir*2048 + d0 + qa1];
        rg[2] = g_U[(size_t)row0*4096 + dir*2048 + d0 + qa0];
        rg[3] = g_U[(size_t)row1*4096 + dir*2048 + d0 + qa1];
        rg[4] = g_XZ[(size_t)row0*8192 + dir*4096 + 2048 + d0 + qa0];
        rg[5] = g_XZ[(size_t)row1*8192 + dir*4096 + 2048 + d0 + qa1];
        rg[6] = g_XDBL[(size_t)row0*256 + dir*128 + 64 + qa0];
        rg[7] = g_XDBL[(size_t)row1*256 + dir*128 + 64 + qa1];
        rg[8] = g_XDBL[(size_t)row0*256 + dir*128 + 80 + qa0];
        rg[9] = g_XDBL[(size_t)row1*256 + dir*128 + 80 + qa1];
    }

    float h = 0.f;
    const int NCH = LSEQ / 32;
    for (int c = 0; c < NCH; c++) {
        __syncthreads();
        sD [la0][qa0] = rg[0]; sD [la1][qa1] = rg[1];
        sU [la0][qa0] = rg[2]; sU [la1][qa1] = rg[3];
        sZ [la0][qa0] = rg[4]; sZ [la1][qa1] = rg[5];
        sB2[la0][qa0] = rg[6]; sB2[la1][qa1] = rg[7];
        sC2[la0][qa0] = rg[8]; sC2[la1][qa1] = rg[9];
        __syncthreads();
        if (c + 1 < NCH) {
            const int lb = (dir == 0) ? (c+1)*32 : (LSEQ - (c+2)*32);
            const int row0 = b*LSEQ + lb + la0;
            const int row1 = b*LSEQ + lb + la1;
            rg[0] = g_DELTA[(size_t)row0*4096 + dir*2048 + d0 + qa0];
            rg[1] = g_DELTA[(size_t)row1*4096 + dir*2048 + d0 + qa1];
            rg[2] = g_U[(size_t)row0*4096 + dir*2048 + d0 + qa0];
            rg[3] = g_U[(size_t)row1*4096 + dir*2048 + d0 + qa1];
            rg[4] = g_XZ[(size_t)row0*8192 + dir*4096 + 2048 + d0 + qa0];
            rg[5] = g_XZ[(size_t)row1*8192 + dir*4096 + 2048 + d0 + qa1];
            rg[6] = g_XDBL[(size_t)row0*256 + dir*128 + 64 + qa0];
            rg[7] = g_XDBL[(size_t)row1*256 + dir*128 + 64 + qa1];
            rg[8] = g_XDBL[(size_t)row0*256 + dir*128 + 80 + qa0];
            rg[9] = g_XDBL[(size_t)row1*256 + dir*128 + 80 + qa1];
        }
        const int lb = (dir == 0) ? c*32 : (LSEQ - (c+1)*32);
#pragma unroll 4
        for (int s = 0; s < 32; s++) {
            const int ll = (dir == 0) ? s : (31 - s);
            const float del = sD[ll][dl];
            const float uu  = sU[ll][dl];
            const float dA  = __expf(del * Acoef);
            h = fmaf(h, dA, del * uu * sB2[ll][n]);
            float py = h * sC2[ll][n];
            py += __shfl_xor_sync(0xffffffffu, py, 8);
            py += __shfl_xor_sync(0xffffffffu, py, 4);
            py += __shfl_xor_sync(0xffffffffu, py, 2);
            py += __shfl_xor_sync(0xffffffffu, py, 1);
            if (n == 0) {
                const float zz = sZ[ll][dl];
                const float y = fmaf(uu, DpV, py);
                const float sig = 1.f / (1.f + __expf(-zz));
                g_YG[(size_t)(b*LSEQ + lb + ll)*4096 + dir*2048 + d] = y * (zz * sig);
            }
        }
    }
}

// ------------------------------------ launch ---------------------------------
extern "C" void kernel_launch(void* const* d_in, const int* in_sizes, int n_in,
                              void* d_out, int out_size)
{
    const float* x      = (const float*)d_in[0];
    const float* inW_f  = (const float*)d_in[1];
    const float* convW_f= (const float*)d_in[2];
    const float* convB_f= (const float*)d_in[3];
    const float* xpW_f  = (const float*)d_in[4];
    const float* dtW_f  = (const float*)d_in[5];
    const float* dtB_f  = (const float*)d_in[6];
    const float* Alog_f = (const float*)d_in[7];
    const float* Dp_f   = (const float*)d_in[8];
    const float* outW_f = (const float*)d_in[9];
    const float* inW_b  = (const float*)d_in[10];
    const float* convW_b= (const float*)d_in[11];
    const float* convB_b= (const float*)d_in[12];
    const float* xpW_b  = (const float*)d_in[13];
    const float* dtW_b  = (const float*)d_in[14];
    const float* dtB_b  = (const float*)d_in[15];
    const float* Alog_b = (const float*)d_in[16];
    const float* Dp_b   = (const float*)d_in[17];
    const float* outW_b = (const float*)d_in[18];
    float* out = (float*)d_out;

    float *XZ, *U, *XDBLP, *XDBL, *DELTA, *YG;
    cudaGetSymbolAddress((void**)&XZ,    g_XZ);
    cudaGetSymbolAddress((void**)&U,     g_U);
    cudaGetSymbolAddress((void**)&XDBLP, g_XDBLP);
    cudaGetSymbolAddress((void**)&XDBL,  g_XDBL);
    cudaGetSymbolAddress((void**)&DELTA, g_DELTA);
    cudaGetSymbolAddress((void**)&YG,    g_YG);

    cudaFuncSetAttribute(hgemm<0>, cudaFuncAttributeMaxDynamicSharedMemorySize, HG_SMEM);
    cudaFuncSetAttribute(hgemm<1>, cudaFuncAttributeMaxDynamicSharedMemorySize, HG_SMEM);
    cudaFuncSetAttribute(hgemm<2>, cudaFuncAttributeMaxDynamicSharedMemorySize, HG_SMEM);

    // 1) input projection, both dirs as one GEMM (N concat: 8192)
    hgemm<0><<<dim3(64,16,1), 256, HG_SMEM>>>(
        x, DMODEL, 0, inW_f, inW_b, DMODEL, 4096, 4096, 0,
        XZ, 8192, DMODEL, nullptr, nullptr, 1.f, 0);

    // 2) depthwise conv + SiLU
    conv_silu_kernel<<<(MROWS*4096)/256, 256>>>(convW_f, convB_f, convW_b, convB_b);

    // 3) x_dbl: N=256 (dir*128, 96 valid), K=2048, split-K=4 + reduce
    hgemm<0><<<dim3(2,16,4), 256, HG_SMEM>>>(
        U, 4096, 2048, xpW_f, xpW_b, DIN, 96, 128, 0,
        XDBLP, 256, DIN, nullptr, nullptr, 1.f, 512);
    reduce_xdbl_kernel<<<(MROWS*256)/256, 256>>>();

    // 4) delta = softplus(dt @ dtW^T + dtB), N=4096 (dir concat), K=64
    hgemm<1><<<dim3(32,16,1), 256, HG_SMEM>>>(
        XDBL, 256, 128, dtW_f, dtW_b, DTR, 2048, 2048, 0,
        DELTA, 4096, DTR, dtB_f, dtB_b, 1.f, 0);

    // 5) selective scan + gating
    scan_kernel<<<dim3(128,2,2), 256>>>(Alog_f, Alog_b, Dp_f, Dp_b);

    // 6) output projection: K=4096 (dir concat on K), out = 0.5*(...)
    hgemm<2><<<dim3(8,16,1), 256, HG_SMEM>>>(
        YG, 4096, 0, outW_f, outW_b, DIN, 1024, 0, 2048,
        out, DMODEL, 4096, nullptr, nullptr, 0.5f, 0);
}